// round 1
// baseline (speedup 1.0000x reference)
#include <cuda_runtime.h>

// DeepLagrangianNetwork: per-row MLP 4 -> 64 -> 64 -> {softplus(2), 1} -> H = L L^T + 1e-9 I
// Strategy: fp32x2 packed FMA (Blackwell fma.rn.f32x2) pairing over the K dimension,
// weights staged in shared (broadcast LDS.128), head fused into the h2 loop.

typedef unsigned long long u64;

__device__ __forceinline__ u64 pk(float a, float b) {
    u64 r; asm("mov.b64 %0, {%1,%2};" : "=l"(r) : "f"(a), "f"(b)); return r;
}
__device__ __forceinline__ u64 fma2(u64 a, u64 b, u64 c) {
    u64 d; asm("fma.rn.f32x2 %0, %1, %2, %3;" : "=l"(d) : "l"(a), "l"(b), "l"(c)); return d;
}
__device__ __forceinline__ u64 add2(u64 a, u64 b) {
    u64 d; asm("add.rn.f32x2 %0, %1, %2;" : "=l"(d) : "l"(a), "l"(b)); return d;
}
__device__ __forceinline__ float2 upk(u64 a) {
    float x, y; asm("mov.b64 {%0,%1}, %2;" : "=f"(x), "=f"(y) : "l"(a));
    return make_float2(x, y);
}

__device__ __forceinline__ float lrelu(float x) { return fmaxf(x, 0.01f * x); }
__device__ __forceinline__ float softplus_f(float x) {
    // log1p(exp(x)) = max(x,0) + log1p(exp(-|x|)), numerically stable
    return fmaxf(x, 0.0f) + log1pf(expf(-fabsf(x)));
}

#define TPB 256

__global__ __launch_bounds__(TPB)
void dln_kernel(const float4* __restrict__ x,
                const float4* __restrict__ W1, const float* __restrict__ b1,
                const float4* __restrict__ W2, const float* __restrict__ b2,
                const float* __restrict__ W_Ld, const float* __restrict__ b_Ld,
                const float* __restrict__ W_Lo, const float* __restrict__ b_Lo,
                float4* __restrict__ out, int n)
{
    __shared__ float4 sW1[64];     // W1 row j (4 inputs)
    __shared__ float  sB1[64];
    __shared__ float4 sW2[1024];   // W2 row-major, 16 float4 per output row
    __shared__ float  sB2[64];
    __shared__ float4 sW3[64];     // (W_Ld0[j], W_Ld1[j], W_Lo[j], 0)
    __shared__ float  sB3[3];

    const int tid = threadIdx.x;
    for (int i = tid; i < 64; i += TPB) {
        sW1[i] = W1[i];
        sB1[i] = b1[i];
        sB2[i] = b2[i];
        sW3[i] = make_float4(W_Ld[i], W_Ld[64 + i], W_Lo[i], 0.0f);
    }
    for (int i = tid; i < 1024; i += TPB) sW2[i] = W2[i];
    if (tid == 0) { sB3[0] = b_Ld[0]; sB3[1] = b_Ld[1]; sB3[2] = b_Lo[0]; }
    __syncthreads();

    const int row = blockIdx.x * TPB + tid;
    if (row >= n) return;

    const float4 q = x[row];
    const u64 q01 = pk(q.x, q.y);
    const u64 q23 = pk(q.z, q.w);

    // ---- layer 1: h1 = lrelu(W1 q + b1), packed into 32 f32x2 pairs ----
    u64 hp[32];
#pragma unroll
    for (int t = 0; t < 32; t++) {
        const int j0 = 2 * t, j1 = 2 * t + 1;
        const float4 w0 = sW1[j0];
        const float4 w1 = sW1[j1];
        u64 a0 = fma2(pk(w0.x, w0.y), q01, pk(sB1[j0], 0.0f));
        a0     = fma2(pk(w0.z, w0.w), q23, a0);
        u64 a1 = fma2(pk(w1.x, w1.y), q01, pk(sB1[j1], 0.0f));
        a1     = fma2(pk(w1.z, w1.w), q23, a1);
        const float2 r0 = upk(a0);
        const float2 r1 = upk(a1);
        hp[t] = pk(lrelu(r0.x + r0.y), lrelu(r1.x + r1.y));
    }

    // ---- layer 2 fused with head: never materialize h2 ----
    float aD0 = sB3[0], aD1 = sB3[1], aO = sB3[2];
#pragma unroll 4
    for (int j = 0; j < 64; j++) {
        const float4* wr = &sW2[j * 16];
        u64 a0 = pk(sB2[j], 0.0f);
        u64 a1 = 0ULL, a2 = 0ULL, a3 = 0ULL;
#pragma unroll
        for (int t = 0; t < 16; t += 2) {
            const float4 w0 = wr[t];
            a0 = fma2(pk(w0.x, w0.y), hp[2 * t],     a0);
            a1 = fma2(pk(w0.z, w0.w), hp[2 * t + 1], a1);
            const float4 w1 = wr[t + 1];
            a2 = fma2(pk(w1.x, w1.y), hp[2 * t + 2], a2);
            a3 = fma2(pk(w1.z, w1.w), hp[2 * t + 3], a3);
        }
        const float2 s = upk(add2(add2(a0, a1), add2(a2, a3)));
        const float h = lrelu(s.x + s.y);
        const float4 w3 = sW3[j];
        aD0 = fmaf(w3.x, h, aD0);
        aD1 = fmaf(w3.y, h, aD1);
        aO  = fmaf(w3.z, h, aO);
    }

    // ---- head: L = [[d0,0],[lo,d1]], H = L L^T + 1e-9 I ----
    const float d0 = softplus_f(aD0);
    const float d1 = softplus_f(aD1);
    const float od = d0 * aO;
    out[row] = make_float4(fmaf(d0, d0, 1e-9f),
                           od,
                           od,
                           fmaf(aO, aO, fmaf(d1, d1, 1e-9f)));
}

extern "C" void kernel_launch(void* const* d_in, const int* in_sizes, int n_in,
                              void* d_out, int out_size)
{
    const float4* x    = (const float4*)d_in[0];
    const float4* W1   = (const float4*)d_in[1];
    const float*  b1   = (const float*)d_in[2];
    const float4* W2   = (const float4*)d_in[3];
    const float*  b2   = (const float*)d_in[4];
    const float*  W_Ld = (const float*)d_in[5];
    const float*  b_Ld = (const float*)d_in[6];
    const float*  W_Lo = (const float*)d_in[7];
    const float*  b_Lo = (const float*)d_in[8];
    float4* out = (float4*)d_out;

    const int n = in_sizes[0] / 4;              // rows
    const int blocks = (n + TPB - 1) / TPB;
    dln_kernel<<<blocks, TPB>>>(x, W1, b1, W2, b2, W_Ld, b_Ld, W_Lo, b_Lo, out, n);
}

// round 3
// speedup vs baseline: 1.1964x; 1.1964x over previous
#include <cuda_runtime.h>

// DeepLagrangianNetwork: per-row MLP 4 -> 64 -> 64 -> {softplus(2), 1} -> H = L L^T + 1e-9 I
// R2: 2 rows per thread so each shared W2 load (LDS.128 broadcast) feeds 4 fma2
// instead of 2 -> FMA pipe becomes the sole bottleneck.

typedef unsigned long long u64;

__device__ __forceinline__ u64 pk(float a, float b) {
    u64 r; asm("mov.b64 %0, {%1,%2};" : "=l"(r) : "f"(a), "f"(b)); return r;
}
__device__ __forceinline__ u64 fma2(u64 a, u64 b, u64 c) {
    u64 d; asm("fma.rn.f32x2 %0, %1, %2, %3;" : "=l"(d) : "l"(a), "l"(b), "l"(c)); return d;
}
__device__ __forceinline__ u64 add2(u64 a, u64 b) {
    u64 d; asm("add.rn.f32x2 %0, %1, %2;" : "=l"(d) : "l"(a), "l"(b)); return d;
}
__device__ __forceinline__ float2 upk(u64 a) {
    float x, y; asm("mov.b64 {%0,%1}, %2;" : "=f"(x), "=f"(y) : "l"(a));
    return make_float2(x, y);
}

__device__ __forceinline__ float lrelu(float x) { return fmaxf(x, 0.01f * x); }
__device__ __forceinline__ float softplus_f(float x) {
    return fmaxf(x, 0.0f) + log1pf(expf(-fabsf(x)));
}

#define TPB 256
#define ROWS_PER_THREAD 2

__global__ __launch_bounds__(TPB, 1)
void dln_kernel(const float4* __restrict__ x,
                const float4* __restrict__ W1, const float* __restrict__ b1,
                const float4* __restrict__ W2, const float* __restrict__ b2,
                const float* __restrict__ W_Ld, const float* __restrict__ b_Ld,
                const float* __restrict__ W_Lo, const float* __restrict__ b_Lo,
                float4* __restrict__ out, int n)
{
    __shared__ float4 sW1[64];     // W1 row j (4 inputs)
    __shared__ float  sB1[64];
    __shared__ float4 sW2[1024];   // W2 row-major, 16 float4 per output row
    __shared__ float  sB2[64];
    __shared__ float4 sW3[64];     // (W_Ld0[j], W_Ld1[j], W_Lo[j], 0)
    __shared__ float  sB3[3];

    const int tid = threadIdx.x;
    for (int i = tid; i < 64; i += TPB) {
        sW1[i] = W1[i];
        sB1[i] = b1[i];
        sB2[i] = b2[i];
        sW3[i] = make_float4(W_Ld[i], W_Ld[64 + i], W_Lo[i], 0.0f);
    }
    for (int i = tid; i < 1024; i += TPB) sW2[i] = W2[i];
    if (tid == 0) { sB3[0] = b_Ld[0]; sB3[1] = b_Ld[1]; sB3[2] = b_Lo[0]; }
    __syncthreads();

    const int base = blockIdx.x * (TPB * ROWS_PER_THREAD);
    const int r0 = base + tid;
    const int r1 = r0 + TPB;
    const bool v0 = (r0 < n);
    const bool v1 = (r1 < n);
    if (!v0) return;

    const float4 qa = x[r0];
    const float4 qb = v1 ? x[r1] : make_float4(0.f, 0.f, 0.f, 0.f);
    const u64 qa01 = pk(qa.x, qa.y), qa23 = pk(qa.z, qa.w);
    const u64 qb01 = pk(qb.x, qb.y), qb23 = pk(qb.z, qb.w);

    // ---- layer 1: h1 = lrelu(W1 q + b1), packed as k-pairs, both rows ----
    u64 hpa[32], hpb[32];
#pragma unroll
    for (int t = 0; t < 32; t++) {
        const int j0 = 2 * t, j1 = 2 * t + 1;
        const float4 w0 = sW1[j0];
        const float4 w1 = sW1[j1];
        const u64 w01 = pk(w0.x, w0.y), w23 = pk(w0.z, w0.w);
        const u64 u01 = pk(w1.x, w1.y), u23 = pk(w1.z, w1.w);
        const u64 bb0 = pk(sB1[j0], 0.0f);
        const u64 bb1 = pk(sB1[j1], 0.0f);

        u64 a0 = fma2(w01, qa01, bb0); a0 = fma2(w23, qa23, a0);
        u64 a1 = fma2(u01, qa01, bb1); a1 = fma2(u23, qa23, a1);
        u64 c0 = fma2(w01, qb01, bb0); c0 = fma2(w23, qb23, c0);
        u64 c1 = fma2(u01, qb01, bb1); c1 = fma2(u23, qb23, c1);

        const float2 ra0 = upk(a0), ra1 = upk(a1);
        const float2 rc0 = upk(c0), rc1 = upk(c1);
        hpa[t] = pk(lrelu(ra0.x + ra0.y), lrelu(ra1.x + ra1.y));
        hpb[t] = pk(lrelu(rc0.x + rc0.y), lrelu(rc1.x + rc1.y));
    }

    // ---- layer 2 fused with head (h2 never materialized), both rows ----
    float aD0a = sB3[0], aD1a = sB3[1], aOa = sB3[2];
    float aD0b = sB3[0], aD1b = sB3[1], aOb = sB3[2];
#pragma unroll 2
    for (int j = 0; j < 64; j++) {
        const float4* wr = &sW2[j * 16];
        const u64 bj = pk(sB2[j], 0.0f);
        u64 a0 = bj, a1 = 0ULL, a2 = 0ULL, a3 = 0ULL;   // row0 chains
        u64 c0 = bj, c1 = 0ULL, c2 = 0ULL, c3 = 0ULL;   // row1 chains
#pragma unroll
        for (int t = 0; t < 16; t += 2) {
            const float4 w0 = wr[t];
            const u64 wA = pk(w0.x, w0.y), wB = pk(w0.z, w0.w);
            a0 = fma2(wA, hpa[2 * t],     a0);
            a1 = fma2(wB, hpa[2 * t + 1], a1);
            c0 = fma2(wA, hpb[2 * t],     c0);
            c1 = fma2(wB, hpb[2 * t + 1], c1);
            const float4 w1 = wr[t + 1];
            const u64 wC = pk(w1.x, w1.y), wD = pk(w1.z, w1.w);
            a2 = fma2(wC, hpa[2 * t + 2], a2);
            a3 = fma2(wD, hpa[2 * t + 3], a3);
            c2 = fma2(wC, hpb[2 * t + 2], c2);
            c3 = fma2(wD, hpb[2 * t + 3], c3);
        }
        const float2 sa = upk(add2(add2(a0, a1), add2(a2, a3)));
        const float2 sb = upk(add2(add2(c0, c1), add2(c2, c3)));
        const float ha = lrelu(sa.x + sa.y);
        const float hb = lrelu(sb.x + sb.y);
        const float4 w3 = sW3[j];
        aD0a = fmaf(w3.x, ha, aD0a);
        aD1a = fmaf(w3.y, ha, aD1a);
        aOa  = fmaf(w3.z, ha, aOa);
        aD0b = fmaf(w3.x, hb, aD0b);
        aD1b = fmaf(w3.y, hb, aD1b);
        aOb  = fmaf(w3.z, hb, aOb);
    }

    // ---- head: L = [[d0,0],[lo,d1]], H = L L^T + 1e-9 I ----
    {
        const float d0 = softplus_f(aD0a);
        const float d1 = softplus_f(aD1a);
        const float od = d0 * aOa;
        out[r0] = make_float4(fmaf(d0, d0, 1e-9f), od, od,
                              fmaf(aOa, aOa, fmaf(d1, d1, 1e-9f)));
    }
    if (v1) {
        const float d0 = softplus_f(aD0b);
        const float d1 = softplus_f(aD1b);
        const float od = d0 * aOb;
        out[r1] = make_float4(fmaf(d0, d0, 1e-9f), od, od,
                              fmaf(aOb, aOb, fmaf(d1, d1, 1e-9f)));
    }
}

extern "C" void kernel_launch(void* const* d_in, const int* in_sizes, int n_in,
                              void* d_out, int out_size)
{
    const float4* x    = (const float4*)d_in[0];
    const float4* W1   = (const float4*)d_in[1];
    const float*  b1   = (const float*)d_in[2];
    const float4* W2   = (const float4*)d_in[3];
    const float*  b2   = (const float*)d_in[4];
    const float*  W_Ld = (const float*)d_in[5];
    const float*  b_Ld = (const float*)d_in[6];
    const float*  W_Lo = (const float*)d_in[7];
    const float*  b_Lo = (const float*)d_in[8];
    float4* out = (float4*)d_out;

    const int n = in_sizes[0] / 4;              // rows
    const int rows_per_block = TPB * ROWS_PER_THREAD;
    const int blocks = (n + rows_per_block - 1) / rows_per_block;
    dln_kernel<<<blocks, TPB>>>(x, W1, b1, W2, b2, W_Ld, b_Ld, W_Lo, b_Lo, out, n);
}

// round 4
// speedup vs baseline: 1.3142x; 1.0984x over previous
#include <cuda_runtime.h>

// DeepLagrangianNetwork: per-row MLP 4 -> 64 -> 64 -> {softplus(2), 1} -> H = L L^T + 1e-9 I
// R3: occupancy fix. TPB=128 with launch_bounds(128,3) -> reg cap 170 -> 12 warps/SM
// (3/SMSP) instead of 8 (2/SMSP). Head fused as packed fma2 over j-pairs.

typedef unsigned long long u64;

__device__ __forceinline__ u64 pk(float a, float b) {
    u64 r; asm("mov.b64 %0, {%1,%2};" : "=l"(r) : "f"(a), "f"(b)); return r;
}
__device__ __forceinline__ u64 fma2(u64 a, u64 b, u64 c) {
    u64 d; asm("fma.rn.f32x2 %0, %1, %2, %3;" : "=l"(d) : "l"(a), "l"(b), "l"(c)); return d;
}
__device__ __forceinline__ u64 add2(u64 a, u64 b) {
    u64 d; asm("add.rn.f32x2 %0, %1, %2;" : "=l"(d) : "l"(a), "l"(b)); return d;
}
__device__ __forceinline__ float2 upk(u64 a) {
    float x, y; asm("mov.b64 {%0,%1}, %2;" : "=f"(x), "=f"(y) : "l"(a));
    return make_float2(x, y);
}

__device__ __forceinline__ float lrelu(float x) { return fmaxf(x, 0.01f * x); }
__device__ __forceinline__ float softplus_f(float x) {
    return fmaxf(x, 0.0f) + log1pf(expf(-fabsf(x)));
}

#define TPB 128
#define ROWS_PER_THREAD 2

__global__ __launch_bounds__(TPB, 3)
void dln_kernel(const float4* __restrict__ x,
                const float4* __restrict__ W1, const float* __restrict__ b1,
                const float4* __restrict__ W2, const float* __restrict__ b2,
                const float* __restrict__ W_Ld, const float* __restrict__ b_Ld,
                const float* __restrict__ W_Lo, const float* __restrict__ b_Lo,
                float4* __restrict__ out, int n)
{
    __shared__ float4 sW1[64];     // W1 row j (4 inputs)
    __shared__ float  sB1[64];
    __shared__ float4 sW2[1024];   // W2 row-major, 16 float4 per output row
    __shared__ float  sB2[64];
    __shared__ u64    sW3x[32];    // (W_Ld[0][2t], W_Ld[0][2t+1])
    __shared__ u64    sW3y[32];    // (W_Ld[1][2t], W_Ld[1][2t+1])
    __shared__ u64    sW3z[32];    // (W_Lo[2t],    W_Lo[2t+1])
    __shared__ float  sB3[3];

    const int tid = threadIdx.x;
    for (int i = tid; i < 64; i += TPB) {
        sW1[i] = W1[i];
        sB1[i] = b1[i];
        sB2[i] = b2[i];
    }
    for (int i = tid; i < 32; i += TPB) {
        sW3x[i] = pk(W_Ld[2 * i],      W_Ld[2 * i + 1]);
        sW3y[i] = pk(W_Ld[64 + 2 * i], W_Ld[64 + 2 * i + 1]);
        sW3z[i] = pk(W_Lo[2 * i],      W_Lo[2 * i + 1]);
    }
    for (int i = tid; i < 1024; i += TPB) sW2[i] = W2[i];
    if (tid == 0) { sB3[0] = b_Ld[0]; sB3[1] = b_Ld[1]; sB3[2] = b_Lo[0]; }
    __syncthreads();

    const int base = blockIdx.x * (TPB * ROWS_PER_THREAD);
    const int r0 = base + tid;
    const int r1 = r0 + TPB;
    const bool v0 = (r0 < n);
    const bool v1 = (r1 < n);
    if (!v0) return;

    const float4 qa = x[r0];
    const float4 qb = v1 ? x[r1] : make_float4(0.f, 0.f, 0.f, 0.f);
    const u64 qa01 = pk(qa.x, qa.y), qa23 = pk(qa.z, qa.w);
    const u64 qb01 = pk(qb.x, qb.y), qb23 = pk(qb.z, qb.w);

    // ---- layer 1: h1 = lrelu(W1 q + b1), packed as k-pairs, both rows ----
    u64 hpa[32], hpb[32];
#pragma unroll 8
    for (int t = 0; t < 32; t++) {
        const int j0 = 2 * t, j1 = 2 * t + 1;
        const float4 w0 = sW1[j0];
        const float4 w1 = sW1[j1];
        const u64 w01 = pk(w0.x, w0.y), w23 = pk(w0.z, w0.w);
        const u64 u01 = pk(w1.x, w1.y), u23 = pk(w1.z, w1.w);
        const u64 bb0 = pk(sB1[j0], 0.0f);
        const u64 bb1 = pk(sB1[j1], 0.0f);

        u64 a0 = fma2(w01, qa01, bb0); a0 = fma2(w23, qa23, a0);
        u64 a1 = fma2(u01, qa01, bb1); a1 = fma2(u23, qa23, a1);
        u64 c0 = fma2(w01, qb01, bb0); c0 = fma2(w23, qb23, c0);
        u64 c1 = fma2(u01, qb01, bb1); c1 = fma2(u23, qb23, c1);

        const float2 ra0 = upk(a0), ra1 = upk(a1);
        const float2 rc0 = upk(c0), rc1 = upk(c1);
        hpa[t] = pk(lrelu(ra0.x + ra0.y), lrelu(ra1.x + ra1.y));
        hpb[t] = pk(lrelu(rc0.x + rc0.y), lrelu(rc1.x + rc1.y));
    }

    // ---- layer 2 fused with packed head (h2 never materialized), both rows ----
    u64 D0a = 0ULL, D1a = 0ULL, Oa = 0ULL;    // packed over j-pairs
    u64 D0b = 0ULL, D1b = 0ULL, Ob = 0ULL;
#pragma unroll 1
    for (int jp = 0; jp < 32; jp++) {
        const int j0 = 2 * jp;
        float ha0, ha1, hb0, hb1;
        // --- j0 ---
        {
            const float4* wr = &sW2[j0 * 16];
            u64 a0 = pk(sB2[j0], 0.0f), a1 = 0ULL;
            u64 c0 = a0, c1 = 0ULL;
#pragma unroll
            for (int t = 0; t < 16; t += 2) {
                const float4 w0 = wr[t];
                const u64 wA = pk(w0.x, w0.y), wB = pk(w0.z, w0.w);
                a0 = fma2(wA, hpa[2 * t],     a0);
                a1 = fma2(wB, hpa[2 * t + 1], a1);
                c0 = fma2(wA, hpb[2 * t],     c0);
                c1 = fma2(wB, hpb[2 * t + 1], c1);
                const float4 w1 = wr[t + 1];
                const u64 wC = pk(w1.x, w1.y), wD = pk(w1.z, w1.w);
                a0 = fma2(wC, hpa[2 * t + 2], a0);
                a1 = fma2(wD, hpa[2 * t + 3], a1);
                c0 = fma2(wC, hpb[2 * t + 2], c0);
                c1 = fma2(wD, hpb[2 * t + 3], c1);
            }
            const float2 sa = upk(add2(a0, a1));
            const float2 sb = upk(add2(c0, c1));
            ha0 = lrelu(sa.x + sa.y);
            hb0 = lrelu(sb.x + sb.y);
        }
        // --- j1 ---
        {
            const float4* wr = &sW2[(j0 + 1) * 16];
            u64 a0 = pk(sB2[j0 + 1], 0.0f), a1 = 0ULL;
            u64 c0 = a0, c1 = 0ULL;
#pragma unroll
            for (int t = 0; t < 16; t += 2) {
                const float4 w0 = wr[t];
                const u64 wA = pk(w0.x, w0.y), wB = pk(w0.z, w0.w);
                a0 = fma2(wA, hpa[2 * t],     a0);
                a1 = fma2(wB, hpa[2 * t + 1], a1);
                c0 = fma2(wA, hpb[2 * t],     c0);
                c1 = fma2(wB, hpb[2 * t + 1], c1);
                const float4 w1 = wr[t + 1];
                const u64 wC = pk(w1.x, w1.y), wD = pk(w1.z, w1.w);
                a0 = fma2(wC, hpa[2 * t + 2], a0);
                a1 = fma2(wD, hpa[2 * t + 3], a1);
                c0 = fma2(wC, hpb[2 * t + 2], c0);
                c1 = fma2(wD, hpb[2 * t + 3], c1);
            }
            const float2 sa = upk(add2(a0, a1));
            const float2 sb = upk(add2(c0, c1));
            ha1 = lrelu(sa.x + sa.y);
            hb1 = lrelu(sb.x + sb.y);
        }
        // --- packed head update for the j-pair ---
        const u64 ha01 = pk(ha0, ha1);
        const u64 hb01 = pk(hb0, hb1);
        const u64 wx = sW3x[jp], wy = sW3y[jp], wz = sW3z[jp];
        D0a = fma2(wx, ha01, D0a);
        D1a = fma2(wy, ha01, D1a);
        Oa  = fma2(wz, ha01, Oa);
        D0b = fma2(wx, hb01, D0b);
        D1b = fma2(wy, hb01, D1b);
        Ob  = fma2(wz, hb01, Ob);
    }

    // ---- head: L = [[d0,0],[lo,d1]], H = L L^T + 1e-9 I ----
    const float bD0 = sB3[0], bD1 = sB3[1], bO = sB3[2];
    {
        const float2 e0 = upk(D0a), e1 = upk(D1a), eo = upk(Oa);
        const float d0 = softplus_f(e0.x + e0.y + bD0);
        const float d1 = softplus_f(e1.x + e1.y + bD1);
        const float lo = eo.x + eo.y + bO;
        const float od = d0 * lo;
        out[r0] = make_float4(fmaf(d0, d0, 1e-9f), od, od,
                              fmaf(lo, lo, fmaf(d1, d1, 1e-9f)));
    }
    if (v1) {
        const float2 e0 = upk(D0b), e1 = upk(D1b), eo = upk(Ob);
        const float d0 = softplus_f(e0.x + e0.y + bD0);
        const float d1 = softplus_f(e1.x + e1.y + bD1);
        const float lo = eo.x + eo.y + bO;
        const float od = d0 * lo;
        out[r1] = make_float4(fmaf(d0, d0, 1e-9f), od, od,
                              fmaf(lo, lo, fmaf(d1, d1, 1e-9f)));
    }
}

extern "C" void kernel_launch(void* const* d_in, const int* in_sizes, int n_in,
                              void* d_out, int out_size)
{
    const float4* x    = (const float4*)d_in[0];
    const float4* W1   = (const float4*)d_in[1];
    const float*  b1   = (const float*)d_in[2];
    const float4* W2   = (const float4*)d_in[3];
    const float*  b2   = (const float*)d_in[4];
    const float*  W_Ld = (const float*)d_in[5];
    const float*  b_Ld = (const float*)d_in[6];
    const float*  W_Lo = (const float*)d_in[7];
    const float*  b_Lo = (const float*)d_in[8];
    float4* out = (float4*)d_out;

    const int n = in_sizes[0] / 4;              // rows
    const int rows_per_block = TPB * ROWS_PER_THREAD;
    const int blocks = (n + rows_per_block - 1) / rows_per_block;
    dln_kernel<<<blocks, TPB>>>(x, W1, b1, W2, b2, W_Ld, b_Ld, W_Lo, b_Lo, out, n);
}

// round 6
// speedup vs baseline: 1.3435x; 1.0223x over previous
#include <cuda_runtime.h>

// DeepLagrangianNetwork: per-row MLP 4 -> 64 -> 64 -> {softplus(2), 1} -> H = L L^T + 1e-9 I
// R5: R3 structure (2 rows/thread, TPB=128, 3 CTAs/SM) + W2 split across two ports:
// even-t chunks via shared (LDS.128 broadcast), odd-t chunks via __constant__
// (LDC/LDCU, separate constant port) to unbind the shared-memory crossbar.

typedef unsigned long long u64;

__constant__ float4 cW2[1024];   // W2 row-major, 16 float4 per output row

__device__ __forceinline__ u64 pk(float a, float b) {
    u64 r; asm("mov.b64 %0, {%1,%2};" : "=l"(r) : "f"(a), "f"(b)); return r;
}
__device__ __forceinline__ u64 fma2(u64 a, u64 b, u64 c) {
    u64 d; asm("fma.rn.f32x2 %0, %1, %2, %3;" : "=l"(d) : "l"(a), "l"(b), "l"(c)); return d;
}
__device__ __forceinline__ u64 add2(u64 a, u64 b) {
    u64 d; asm("add.rn.f32x2 %0, %1, %2;" : "=l"(d) : "l"(a), "l"(b)); return d;
}
__device__ __forceinline__ float2 upk(u64 a) {
    float x, y; asm("mov.b64 {%0,%1}, %2;" : "=f"(x), "=f"(y) : "l"(a));
    return make_float2(x, y);
}

__device__ __forceinline__ float lrelu(float x) { return fmaxf(x, 0.01f * x); }
__device__ __forceinline__ float softplus_f(float x) {
    return fmaxf(x, 0.0f) + log1pf(expf(-fabsf(x)));
}

#define TPB 128
#define ROWS_PER_THREAD 2

__global__ __launch_bounds__(TPB, 3)
void dln_kernel(const float4* __restrict__ x,
                const float4* __restrict__ W1, const float* __restrict__ b1,
                const float4* __restrict__ W2, const float* __restrict__ b2,
                const float* __restrict__ W_Ld, const float* __restrict__ b_Ld,
                const float* __restrict__ W_Lo, const float* __restrict__ b_Lo,
                float4* __restrict__ out, int n)
{
    __shared__ float4 sW1[64];     // W1 row j (4 inputs)
    __shared__ float  sB1[64];
    __shared__ float4 sW2[1024];   // W2 row-major (even-t chunks consumed from here)
    __shared__ float  sB2[64];
    __shared__ u64    sW3x[32];    // (W_Ld[0][2t], W_Ld[0][2t+1])
    __shared__ u64    sW3y[32];    // (W_Ld[1][2t], W_Ld[1][2t+1])
    __shared__ u64    sW3z[32];    // (W_Lo[2t],    W_Lo[2t+1])
    __shared__ float  sB3[3];

    const int tid = threadIdx.x;
    for (int i = tid; i < 64; i += TPB) {
        sW1[i] = W1[i];
        sB1[i] = b1[i];
        sB2[i] = b2[i];
    }
    for (int i = tid; i < 32; i += TPB) {
        sW3x[i] = pk(W_Ld[2 * i],      W_Ld[2 * i + 1]);
        sW3y[i] = pk(W_Ld[64 + 2 * i], W_Ld[64 + 2 * i + 1]);
        sW3z[i] = pk(W_Lo[2 * i],      W_Lo[2 * i + 1]);
    }
    for (int i = tid; i < 1024; i += TPB) sW2[i] = W2[i];
    if (tid == 0) { sB3[0] = b_Ld[0]; sB3[1] = b_Ld[1]; sB3[2] = b_Lo[0]; }
    __syncthreads();

    const int base = blockIdx.x * (TPB * ROWS_PER_THREAD);
    const int r0 = base + tid;
    const int r1 = r0 + TPB;
    const bool v0 = (r0 < n);
    const bool v1 = (r1 < n);
    if (!v0) return;

    const float4 qa = x[r0];
    const float4 qb = v1 ? x[r1] : make_float4(0.f, 0.f, 0.f, 0.f);
    const u64 qa01 = pk(qa.x, qa.y), qa23 = pk(qa.z, qa.w);
    const u64 qb01 = pk(qb.x, qb.y), qb23 = pk(qb.z, qb.w);

    // ---- layer 1: h1 = lrelu(W1 q + b1), packed as k-pairs, both rows ----
    u64 hpa[32], hpb[32];
#pragma unroll 8
    for (int t = 0; t < 32; t++) {
        const int j0 = 2 * t, j1 = 2 * t + 1;
        const float4 w0 = sW1[j0];
        const float4 w1 = sW1[j1];
        const u64 w01 = pk(w0.x, w0.y), w23 = pk(w0.z, w0.w);
        const u64 u01 = pk(w1.x, w1.y), u23 = pk(w1.z, w1.w);
        const u64 bb0 = pk(sB1[j0], 0.0f);
        const u64 bb1 = pk(sB1[j1], 0.0f);

        u64 a0 = fma2(w01, qa01, bb0); a0 = fma2(w23, qa23, a0);
        u64 a1 = fma2(u01, qa01, bb1); a1 = fma2(u23, qa23, a1);
        u64 c0 = fma2(w01, qb01, bb0); c0 = fma2(w23, qb23, c0);
        u64 c1 = fma2(u01, qb01, bb1); c1 = fma2(u23, qb23, c1);

        const float2 ra0 = upk(a0), ra1 = upk(a1);
        const float2 rc0 = upk(c0), rc1 = upk(c1);
        hpa[t] = pk(lrelu(ra0.x + ra0.y), lrelu(ra1.x + ra1.y));
        hpb[t] = pk(lrelu(rc0.x + rc0.y), lrelu(rc1.x + rc1.y));
    }

    // ---- layer 2 fused with packed head (h2 never materialized), both rows ----
    u64 D0a = 0ULL, D1a = 0ULL, Oa = 0ULL;    // packed over j-pairs
    u64 D0b = 0ULL, D1b = 0ULL, Ob = 0ULL;
#pragma unroll 1
    for (int jp = 0; jp < 32; jp++) {
        const int j0 = 2 * jp;
        float ha0, ha1, hb0, hb1;
        // --- j0 ---
        {
            const float4* wrS = &sW2[j0 * 16];   // shared port
            const float4* wrC = &cW2[j0 * 16];   // constant port
            u64 a0 = pk(sB2[j0], 0.0f), a1 = 0ULL;
            u64 c0 = a0, c1 = 0ULL;
#pragma unroll
            for (int t = 0; t < 16; t += 2) {
                const float4 w0 = wrS[t];
                const u64 wA = pk(w0.x, w0.y), wB = pk(w0.z, w0.w);
                a0 = fma2(wA, hpa[2 * t],     a0);
                a1 = fma2(wB, hpa[2 * t + 1], a1);
                c0 = fma2(wA, hpb[2 * t],     c0);
                c1 = fma2(wB, hpb[2 * t + 1], c1);
                const float4 w1 = wrC[t + 1];
                const u64 wC = pk(w1.x, w1.y), wD = pk(w1.z, w1.w);
                a0 = fma2(wC, hpa[2 * t + 2], a0);
                a1 = fma2(wD, hpa[2 * t + 3], a1);
                c0 = fma2(wC, hpb[2 * t + 2], c0);
                c1 = fma2(wD, hpb[2 * t + 3], c1);
            }
            const float2 sa = upk(add2(a0, a1));
            const float2 sb = upk(add2(c0, c1));
            ha0 = lrelu(sa.x + sa.y);
            hb0 = lrelu(sb.x + sb.y);
        }
        // --- j1 ---
        {
            const float4* wrS = &sW2[(j0 + 1) * 16];
            const float4* wrC = &cW2[(j0 + 1) * 16];
            u64 a0 = pk(sB2[j0 + 1], 0.0f), a1 = 0ULL;
            u64 c0 = a0, c1 = 0ULL;
#pragma unroll
            for (int t = 0; t < 16; t += 2) {
                const float4 w0 = wrS[t];
                const u64 wA = pk(w0.x, w0.y), wB = pk(w0.z, w0.w);
                a0 = fma2(wA, hpa[2 * t],     a0);
                a1 = fma2(wB, hpa[2 * t + 1], a1);
                c0 = fma2(wA, hpb[2 * t],     c0);
                c1 = fma2(wB, hpb[2 * t + 1], c1);
                const float4 w1 = wrC[t + 1];
                const u64 wC = pk(w1.x, w1.y), wD = pk(w1.z, w1.w);
                a0 = fma2(wC, hpa[2 * t + 2], a0);
                a1 = fma2(wD, hpa[2 * t + 3], a1);
                c0 = fma2(wC, hpb[2 * t + 2], c0);
                c1 = fma2(wD, hpb[2 * t + 3], c1);
            }
            const float2 sa = upk(add2(a0, a1));
            const float2 sb = upk(add2(c0, c1));
            ha1 = lrelu(sa.x + sa.y);
            hb1 = lrelu(sb.x + sb.y);
        }
        // --- packed head update for the j-pair ---
        const u64 ha01 = pk(ha0, ha1);
        const u64 hb01 = pk(hb0, hb1);
        const u64 wx = sW3x[jp], wy = sW3y[jp], wz = sW3z[jp];
        D0a = fma2(wx, ha01, D0a);
        D1a = fma2(wy, ha01, D1a);
        Oa  = fma2(wz, ha01, Oa);
        D0b = fma2(wx, hb01, D0b);
        D1b = fma2(wy, hb01, D1b);
        Ob  = fma2(wz, hb01, Ob);
    }

    // ---- head: L = [[d0,0],[lo,d1]], H = L L^T + 1e-9 I ----
    const float bD0 = sB3[0], bD1 = sB3[1], bO = sB3[2];
    {
        const float2 e0 = upk(D0a), e1 = upk(D1a), eo = upk(Oa);
        const float d0 = softplus_f(e0.x + e0.y + bD0);
        const float d1 = softplus_f(e1.x + e1.y + bD1);
        const float lo = eo.x + eo.y + bO;
        const float od = d0 * lo;
        out[r0] = make_float4(fmaf(d0, d0, 1e-9f), od, od,
                              fmaf(lo, lo, fmaf(d1, d1, 1e-9f)));
    }
    if (v1) {
        const float2 e0 = upk(D0b), e1 = upk(D1b), eo = upk(Ob);
        const float d0 = softplus_f(e0.x + e0.y + bD0);
        const float d1 = softplus_f(e1.x + e1.y + bD1);
        const float lo = eo.x + eo.y + bO;
        const float od = d0 * lo;
        out[r1] = make_float4(fmaf(d0, d0, 1e-9f), od, od,
                              fmaf(lo, lo, fmaf(d1, d1, 1e-9f)));
    }
}

extern "C" void kernel_launch(void* const* d_in, const int* in_sizes, int n_in,
                              void* d_out, int out_size)
{
    const float4* x    = (const float4*)d_in[0];
    const float4* W1   = (const float4*)d_in[1];
    const float*  b1   = (const float*)d_in[2];
    const float4* W2   = (const float4*)d_in[3];
    const float*  b2   = (const float*)d_in[4];
    const float*  W_Ld = (const float*)d_in[5];
    const float*  b_Ld = (const float*)d_in[6];
    const float*  W_Lo = (const float*)d_in[7];
    const float*  b_Lo = (const float*)d_in[8];
    float4* out = (float4*)d_out;

    // Stage W2 into constant memory (device-to-device async copy: graph-capturable,
    // no allocation).
    cudaMemcpyToSymbolAsync(cW2, d_in[3], 1024 * sizeof(float4), 0,
                            cudaMemcpyDeviceToDevice);

    const int n = in_sizes[0] / 4;              // rows
    const int rows_per_block = TPB * ROWS_PER_THREAD;
    const int blocks = (n + rows_per_block - 1) / rows_per_block;
    dln_kernel<<<blocks, TPB>>>(x, W1, b1, W2, b2, W_Ld, b_Ld, W_Lo, b_Lo, out, n);
}

// round 8
// speedup vs baseline: 2.1151x; 1.5743x over previous
#include <cuda_runtime.h>
#include <cuda_bf16.h>

typedef unsigned long long u64;
typedef unsigned int u32;

// ---------- helpers ----------
__device__ __forceinline__ u64 pk(float a, float b) {
    u64 r; asm("mov.b64 %0, {%1,%2};" : "=l"(r) : "f"(a), "f"(b)); return r;
}
__device__ __forceinline__ u64 fma2(u64 a, u64 b, u64 c) {
    u64 d; asm("fma.rn.f32x2 %0, %1, %2, %3;" : "=l"(d) : "l"(a), "l"(b), "l"(c)); return d;
}
__device__ __forceinline__ float2 upk(u64 a) {
    float x, y; asm("mov.b64 {%0,%1}, %2;" : "=f"(x), "=f"(y) : "l"(a));
    return make_float2(x, y);
}
__device__ __forceinline__ float lrelu(float x) { return fmaxf(x, 0.01f * x); }
__device__ __forceinline__ float softplus_f(float x) {
    return fmaxf(x, 0.0f) + log1pf(expf(-fabsf(x)));
}
__device__ __forceinline__ u32 smem_u32(const void* p) {
    u32 a; asm("{ .reg .u64 t; cvta.to.shared.u64 t, %1; cvt.u32.u64 %0, t; }"
               : "=r"(a) : "l"(p)); return a;
}
// pack two f32 -> bf16x2: low half = lo_val, high half = hi_val
__device__ __forceinline__ u32 cvt_bf2(float lo_val, float hi_val) {
    u32 r; asm("cvt.rn.bf16x2.f32 %0, %1, %2;" : "=r"(r) : "f"(hi_val), "f"(lo_val));
    return r;
}
__device__ __forceinline__ float bf_lo_f(u32 v) { return __uint_as_float(v << 16); }
__device__ __forceinline__ float bf_hi_f(u32 v) { return __uint_as_float(v & 0xffff0000u); }

__device__ __forceinline__ void ldsm4(u32* r, u32 addr) {
    asm volatile("ldmatrix.sync.aligned.m8n8.x4.shared.b16 {%0,%1,%2,%3}, [%4];"
                 : "=r"(r[0]), "=r"(r[1]), "=r"(r[2]), "=r"(r[3]) : "r"(addr));
}
__device__ __forceinline__ void mma_bf16(float* d, const u32* a, const u32* b) {
    asm volatile(
        "mma.sync.aligned.m16n8k16.row.col.f32.bf16.bf16.f32 "
        "{%0,%1,%2,%3}, {%4,%5,%6,%7}, {%8,%9}, {%0,%1,%2,%3};"
        : "+f"(d[0]), "+f"(d[1]), "+f"(d[2]), "+f"(d[3])
        : "r"(a[0]), "r"(a[1]), "r"(a[2]), "r"(a[3]), "r"(b[0]), "r"(b[1]));
}
__device__ __forceinline__ u32 swz(u32 off) { return off ^ ((off >> 3) & 0x70); }

#define TPB 128
#define TILE_M 128
#define GRIDN 444   // 148 SMs * 3 CTAs

__global__ __launch_bounds__(TPB, 3)
void dln_mma_kernel(const float4* __restrict__ x,
                    const float4* __restrict__ W1, const float* __restrict__ b1,
                    const float* __restrict__ W2f, const float* __restrict__ b2,
                    const float* __restrict__ W_Ld, const float* __restrict__ b_Ld,
                    const float* __restrict__ W_Lo, const float* __restrict__ b_Lo,
                    float4* __restrict__ out, int n, int num_tiles)
{
    // h1 staging: 128 rows x 64 cols bf16 = 16KB each (hi, lo), swizzled
    __shared__ __align__(128) unsigned char sAhi[16384];
    __shared__ __align__(128) unsigned char sAlo[16384];
    __shared__ u64    sBlo[8 * 4 * 32];    // B-lo fragments [nt*4+kc][lane]
    __shared__ float4 sW1[64];
    __shared__ float  sB1[64];
    __shared__ u64    sB2p[32];            // (b2[2i], b2[2i+1])
    __shared__ u64    sW3x[32], sW3y[32], sW3z[32];
    __shared__ float  sB3[3];

    const int tid = threadIdx.x;
    const int wid = tid >> 5;
    const int lane = tid & 31;
    const int g = lane >> 2;     // group id (row within 8)
    const int t = lane & 3;      // thread in group (col pair)

    // ---- stage small weights ----
    for (int i = tid; i < 64; i += TPB) {
        sW1[i] = W1[i];
        sB1[i] = b1[i];
    }
    for (int i = tid; i < 32; i += TPB) {
        sB2p[i] = pk(b2[2 * i],          b2[2 * i + 1]);
        sW3x[i] = pk(W_Ld[2 * i],        W_Ld[2 * i + 1]);
        sW3y[i] = pk(W_Ld[64 + 2 * i],   W_Ld[64 + 2 * i + 1]);
        sW3z[i] = pk(W_Lo[2 * i],        W_Lo[2 * i + 1]);
    }
    if (tid == 0) { sB3[0] = b_Ld[0]; sB3[1] = b_Ld[1]; sB3[2] = b_Lo[0]; }

    // ---- build B fragments: hi in registers, lo in SMEM table ----
    // B[k][n] = W2[n][k];  frag (nt,kc): b0={B[k0][n],B[k0+1][n]}, b1={B[k0+8][n],B[k0+9][n]}
    // with n = nt*8+g, k0 = kc*16+2t
    u32 bhi[8][4][2];
#pragma unroll
    for (int nt = 0; nt < 8; nt++) {
#pragma unroll
        for (int kc = 0; kc < 4; kc++) {
            const int nn = nt * 8 + g;
            const int k0 = kc * 16 + 2 * t;
            const float f0 = W2f[nn * 64 + k0];
            const float f1 = W2f[nn * 64 + k0 + 1];
            const float f2 = W2f[nn * 64 + k0 + 8];
            const float f3 = W2f[nn * 64 + k0 + 9];
            const u32 h0 = cvt_bf2(f0, f1);
            const u32 h1 = cvt_bf2(f2, f3);
            bhi[nt][kc][0] = h0;
            bhi[nt][kc][1] = h1;
            if (wid == 0) {
                const u32 l0 = cvt_bf2(f0 - bf_lo_f(h0), f1 - bf_hi_f(h0));
                const u32 l1 = cvt_bf2(f2 - bf_lo_f(h1), f3 - bf_hi_f(h1));
                sBlo[(nt * 4 + kc) * 32 + lane] = ((u64)l1 << 32) | (u64)l0;
            }
        }
    }
    __syncthreads();

    const u32 aHiB = smem_u32(sAhi);
    const u32 aLoB = smem_u32(sAlo);
    // ldmatrix per-lane address offsets for this warp: row = wid*32 + mt*16 + (lane&15),
    // byte col = kc*32 + (lane>>4)*16
    const int lrow = (lane & 15);
    const int lcol16 = (lane >> 4) * 16;

    int tile = blockIdx.x;
    float4 xv = make_float4(0.f, 0.f, 0.f, 0.f);
    if (tile < num_tiles) {
        const int r = tile * TILE_M + tid;
        if (r < n) xv = x[r];
    }

    for (; tile < num_tiles; tile += GRIDN) {
        // ---- layer 1 (FFMA) -> bf16 hi/lo staged to SMEM (all 64 cols!) ----
        {
            const u64 q01 = pk(xv.x, xv.y), q23 = pk(xv.z, xv.w);
#pragma unroll
            for (int it = 0; it < 8; it++) {          // 8 cols per iteration, 64 total
                u32 hi4[4], lo4[4];
#pragma unroll
                for (int p = 0; p < 4; p++) {
                    const int j0 = it * 8 + 2 * p;
                    const float4 w0 = sW1[j0];
                    const float4 w1 = sW1[j0 + 1];
                    u64 a0 = fma2(pk(w0.x, w0.y), q01, pk(sB1[j0], 0.f));
                    a0     = fma2(pk(w0.z, w0.w), q23, a0);
                    u64 a1 = fma2(pk(w1.x, w1.y), q01, pk(sB1[j0 + 1], 0.f));
                    a1     = fma2(pk(w1.z, w1.w), q23, a1);
                    const float2 r0 = upk(a0), r1 = upk(a1);
                    const float h0 = lrelu(r0.x + r0.y);
                    const float h1 = lrelu(r1.x + r1.y);
                    const u32 hp = cvt_bf2(h0, h1);
                    hi4[p] = hp;
                    lo4[p] = cvt_bf2(h0 - bf_lo_f(hp), h1 - bf_hi_f(hp));
                }
                const u32 off = swz((u32)(tid * 128 + it * 16));
                *reinterpret_cast<uint4*>(sAhi + off) = make_uint4(hi4[0], hi4[1], hi4[2], hi4[3]);
                *reinterpret_cast<uint4*>(sAlo + off) = make_uint4(lo4[0], lo4[1], lo4[2], lo4[3]);
            }
        }
        // prefetch next tile's x
        {
            const int ntile = tile + GRIDN;
            float4 xn = make_float4(0.f, 0.f, 0.f, 0.f);
            if (ntile < num_tiles) {
                const int r2 = ntile * TILE_M + tid;
                if (r2 < n) xn = x[r2];
            }
            xv = xn;
        }
        __syncthreads();

        // ---- MMA phase: warp handles rows [wid*32, wid*32+32) as 2 m-tiles ----
#pragma unroll
        for (int mt = 0; mt < 2; mt++) {
            const int mrow0 = wid * 32 + mt * 16;
            float acc[8][4];
#pragma unroll
            for (int nt = 0; nt < 8; nt++) {
                acc[nt][0] = 0.f; acc[nt][1] = 0.f; acc[nt][2] = 0.f; acc[nt][3] = 0.f;
            }
#pragma unroll
            for (int kc = 0; kc < 4; kc++) {
                const u32 off = swz((u32)((mrow0 + lrow) * 128 + kc * 32 + lcol16));
                u32 ahi[4], alo[4];
                ldsm4(ahi, aHiB + off);
                ldsm4(alo, aLoB + off);
#pragma unroll
                for (int nt = 0; nt < 8; nt++) {
                    mma_bf16(acc[nt], ahi, bhi[nt][kc]);
                    const u64 bl = sBlo[(nt * 4 + kc) * 32 + lane];
                    u32 blr[2] = { (u32)bl, (u32)(bl >> 32) };
                    mma_bf16(acc[nt], ahi, blr);
                    mma_bf16(acc[nt], alo, bhi[nt][kc]);
                }
            }

            // ---- epilogue for this m-tile ----
            // thread holds D[g][j], D[g][j+1], D[g+8][j], D[g+8][j+1] for j = nt*8+2t
            u64 D0a = 0ULL, D1a = 0ULL, Oa = 0ULL;
            u64 D0b = 0ULL, D1b = 0ULL, Ob = 0ULL;
#pragma unroll
            for (int nt = 0; nt < 8; nt++) {
                const int i = nt * 4 + t;
                const float2 bb = upk(sB2p[i]);
                const u64 ha = pk(lrelu(acc[nt][0] + bb.x), lrelu(acc[nt][1] + bb.y));
                const u64 hb = pk(lrelu(acc[nt][2] + bb.x), lrelu(acc[nt][3] + bb.y));
                const u64 wx = sW3x[i], wy = sW3y[i], wz = sW3z[i];
                D0a = fma2(wx, ha, D0a); D1a = fma2(wy, ha, D1a); Oa = fma2(wz, ha, Oa);
                D0b = fma2(wx, hb, D0b); D1b = fma2(wy, hb, D1b); Ob = fma2(wz, hb, Ob);
            }
            float v0, v1, v2, v3, v4, v5;
            { const float2 e = upk(D0a); v0 = e.x + e.y; }
            { const float2 e = upk(D1a); v1 = e.x + e.y; }
            { const float2 e = upk(Oa);  v2 = e.x + e.y; }
            { const float2 e = upk(D0b); v3 = e.x + e.y; }
            { const float2 e = upk(D1b); v4 = e.x + e.y; }
            { const float2 e = upk(Ob);  v5 = e.x + e.y; }
            v0 += __shfl_xor_sync(0xffffffffu, v0, 1); v0 += __shfl_xor_sync(0xffffffffu, v0, 2);
            v1 += __shfl_xor_sync(0xffffffffu, v1, 1); v1 += __shfl_xor_sync(0xffffffffu, v1, 2);
            v2 += __shfl_xor_sync(0xffffffffu, v2, 1); v2 += __shfl_xor_sync(0xffffffffu, v2, 2);
            v3 += __shfl_xor_sync(0xffffffffu, v3, 1); v3 += __shfl_xor_sync(0xffffffffu, v3, 2);
            v4 += __shfl_xor_sync(0xffffffffu, v4, 1); v4 += __shfl_xor_sync(0xffffffffu, v4, 2);
            v5 += __shfl_xor_sync(0xffffffffu, v5, 1); v5 += __shfl_xor_sync(0xffffffffu, v5, 2);

            if (t == 0) {
                const int rowA = tile * TILE_M + mrow0 + g;
                const int rowB = rowA + 8;
                if (rowA < n) {
                    const float d0 = softplus_f(v0 + sB3[0]);
                    const float d1 = softplus_f(v1 + sB3[1]);
                    const float lo = v2 + sB3[2];
                    const float od = d0 * lo;
                    out[rowA] = make_float4(fmaf(d0, d0, 1e-9f), od, od,
                                            fmaf(lo, lo, fmaf(d1, d1, 1e-9f)));
                }
                if (rowB < n) {
                    const float d0 = softplus_f(v3 + sB3[0]);
                    const float d1 = softplus_f(v4 + sB3[1]);
                    const float lo = v5 + sB3[2];
                    const float od = d0 * lo;
                    out[rowB] = make_float4(fmaf(d0, d0, 1e-9f), od, od,
                                            fmaf(lo, lo, fmaf(d1, d1, 1e-9f)));
                }
            }
        }
        __syncthreads();   // staging reuse barrier
    }
}

extern "C" void kernel_launch(void* const* d_in, const int* in_sizes, int n_in,
                              void* d_out, int out_size)
{
    const float4* x    = (const float4*)d_in[0];
    const float4* W1   = (const float4*)d_in[1];
    const float*  b1   = (const float*)d_in[2];
    const float*  W2   = (const float*)d_in[3];
    const float*  b2   = (const float*)d_in[4];
    const float*  W_Ld = (const float*)d_in[5];
    const float*  b_Ld = (const float*)d_in[6];
    const float*  W_Lo = (const float*)d_in[7];
    const float*  b_Lo = (const float*)d_in[8];
    float4* out = (float4*)d_out;

    const int n = in_sizes[0] / 4;                  // rows
    const int num_tiles = (n + TILE_M - 1) / TILE_M;
    const int grid = (num_tiles < GRIDN) ? num_tiles : GRIDN;
    dln_mma_kernel<<<grid, TPB>>>(x, W1, b1, W2, b2, W_Ld, b_Ld, W_Lo, b_Lo,
                                  out, n, num_tiles);
}